// round 5
// baseline (speedup 1.0000x reference)
#include <cuda_runtime.h>
#include <math.h>
#include <stdint.h>

#define V 32000
#define H 1024
#define T 32
#define B 64
#define SOS_INDEX 1
#define EOS_INDEX 2
#define GATES (4*H)

// Persistent decode state (no allocations allowed)
__device__ float g_x[B*H];       // current input embedding
__device__ float g_h[B*H];       // hidden state
__device__ float g_c[B*H];       // cell state
__device__ float g_gates[B*GATES];

// ---------------------------------------------------------------------------
__global__ void init_kernel(const float* __restrict__ E,
                            const float* __restrict__ eh,
                            const float* __restrict__ ec) {
    int i = blockIdx.x * blockDim.x + threadIdx.x;   // 0 .. B*H
    int k = i & (H - 1);
    g_x[i] = E[SOS_INDEX * H + k];
    g_h[i] = eh[i];
    g_c[i] = ec[i];
}

// ---------------------------------------------------------------------------
// TF32 helpers (3xTF32 fp32 emulation)
// ---------------------------------------------------------------------------
__device__ __forceinline__ uint32_t f2tf32(float x) {
    uint32_t r;
    asm("cvt.rna.tf32.f32 %0, %1;" : "=r"(r) : "f"(x));
    return r;
}
__device__ __forceinline__ void split_tf32(float x, float& hi, float& lo) {
    hi = __uint_as_float(f2tf32(x));
    lo = __uint_as_float(f2tf32(x - hi));
}
__device__ __forceinline__ void mma_tf32(float c[4], float4 a, float2 b) {
    asm volatile(
        "mma.sync.aligned.m16n8k8.row.col.f32.tf32.tf32.f32 "
        "{%0,%1,%2,%3}, {%4,%5,%6,%7}, {%8,%9}, {%0,%1,%2,%3};"
        : "+f"(c[0]), "+f"(c[1]), "+f"(c[2]), "+f"(c[3])
        : "r"(__float_as_uint(a.x)), "r"(__float_as_uint(a.y)),
          "r"(__float_as_uint(a.z)), "r"(__float_as_uint(a.w)),
          "r"(__float_as_uint(b.x)), "r"(__float_as_uint(b.y)));
}

// ---------------------------------------------------------------------------
// Tensor-core GEMM: C[64 x N] = A[64 x KTOT] * W[N x KTOT]^T + bias
// hi/lo tf32 split is done ONCE at the load stage, stored directly in the
// MMA fragment layout:
//   AF[half][kb][mw][lane][reg0..3]  (m16k8 A fragment per lane, LDS.128)
//   BF[half][kb][nw8][lane][reg0..1] (k8n8  B fragment per lane, LDS.64)
// Inner loop is pure vector-LDS + HMMA. Register prefetch of next gmem tile.
// ---------------------------------------------------------------------------
#define BK 32

template<int KTOT, int BN, bool CONCAT>
__global__ __launch_bounds__(256)
void mma_gemm(const float* __restrict__ Wa, const float* __restrict__ Wb,
              const float* __restrict__ bias1, const float* __restrict__ bias2,
              float* __restrict__ out, int ldc) {
    constexpr int NF  = BN / 16;          // 8-wide n fragments per warp
    constexpr int NW8 = BN / 8;           // total 8-wide n fragments
    constexpr int BR  = BN / 32;          // B loader row chunks

    __shared__ __align__(16) float AF[2][4][4][32][4];    // 16 KB
    __shared__ __align__(16) float BF[2][4][NW8][32][2];  // 16 KB @BN=64

    const int n0blk = blockIdx.x * BN;
    const int tid   = threadIdx.x;
    const int warp  = tid >> 5;
    const int lane  = tid & 31;
    const int gid   = lane >> 2;
    const int tig   = lane & 3;

    const int mw     = warp >> 1;              // warp M tile (0..3) = m0/16
    const int m0     = mw * 16;
    const int nwbase = (warp & 1) * (NW8 / 2); // warp n8-fragment base
    const int n0w    = nwbase * 8;

    const int lm   = tid >> 3;             // loader row 0..31
    const int lk4  = (tid & 7) * 4;        // loader k offset (float4)
    const int kb_l = lk4 >> 3;             // loader kb (0..3)
    const int rg_l = (lk4 >> 2) & 1;       // loader half-of-k8 (0/1)

    float4 aR[2];
    float4 bR[BR];

    auto gload = [&](int k0) {
        const int kg = k0 + lk4;
        #pragma unroll
        for (int r = 0; r < 2; r++) {
            int m = lm + r * 32;
            const float* src = CONCAT
                ? ((kg < H) ? (g_x + m * H + kg) : (g_h + m * H + (kg - H)))
                : (g_h + m * H + kg);
            aR[r] = *reinterpret_cast<const float4*>(src);
        }
        #pragma unroll
        for (int r = 0; r < BR; r++) {
            int n = lm + r * 32;
            const float* src = CONCAT
                ? ((kg < H) ? (Wa + (size_t)(n0blk + n) * H + kg)
                            : (Wb + (size_t)(n0blk + n) * H + (kg - H)))
                : (Wa + (size_t)(n0blk + n) * KTOT + kg);
            bR[r] = *reinterpret_cast<const float4*>(src);
        }
    };

    auto store_split = [&]() {
        // A: element (m, lk4+j) -> AF[h][kb][m>>4][(m&7)*4+j][((m>>3)&1)+2*rg_l]
        #pragma unroll
        for (int r = 0; r < 2; r++) {
            int m    = lm + r * 32;
            int amw  = m >> 4;
            int areg = ((m >> 3) & 1) + 2 * rg_l;
            int al0  = (m & 7) * 4;
            float v[4] = {aR[r].x, aR[r].y, aR[r].z, aR[r].w};
            #pragma unroll
            for (int j = 0; j < 4; j++) {
                float hi, lo; split_tf32(v[j], hi, lo);
                AF[0][kb_l][amw][al0 + j][areg] = hi;
                AF[1][kb_l][amw][al0 + j][areg] = lo;
            }
        }
        // B: element (n, lk4+j) -> BF[h][kb][n>>3][(n&7)*4+j][rg_l]
        #pragma unroll
        for (int r = 0; r < BR; r++) {
            int n    = lm + r * 32;
            int nw8  = n >> 3;
            int bl0  = (n & 7) * 4;
            float v[4] = {bR[r].x, bR[r].y, bR[r].z, bR[r].w};
            #pragma unroll
            for (int j = 0; j < 4; j++) {
                float hi, lo; split_tf32(v[j], hi, lo);
                BF[0][kb_l][nw8][bl0 + j][rg_l] = hi;
                BF[1][kb_l][nw8][bl0 + j][rg_l] = lo;
            }
        }
    };

    float c[NF][4];
    #pragma unroll
    for (int nf = 0; nf < NF; nf++)
        #pragma unroll
        for (int j = 0; j < 4; j++) c[nf][j] = 0.f;

    gload(0);
    for (int k0 = 0; k0 < KTOT; k0 += BK) {
        store_split();
        __syncthreads();
        if (k0 + BK < KTOT) gload(k0 + BK);    // prefetch next tile into regs

        #pragma unroll
        for (int ks = 0; ks < 4; ks++) {
            float4 ah = *reinterpret_cast<const float4*>(AF[0][ks][mw][lane]);
            float4 al = *reinterpret_cast<const float4*>(AF[1][ks][mw][lane]);
            float2 bh[NF], bl[NF];
            #pragma unroll
            for (int nf = 0; nf < NF; nf++) {
                bh[nf] = *reinterpret_cast<const float2*>(BF[0][ks][nwbase + nf][lane]);
                bl[nf] = *reinterpret_cast<const float2*>(BF[1][ks][nwbase + nf][lane]);
            }
            // pass-major ordering: long reuse distance on each c[nf] chain
            #pragma unroll
            for (int nf = 0; nf < NF; nf++) mma_tf32(c[nf], al, bh[nf]);
            #pragma unroll
            for (int nf = 0; nf < NF; nf++) mma_tf32(c[nf], ah, bl[nf]);
            #pragma unroll
            for (int nf = 0; nf < NF; nf++) mma_tf32(c[nf], ah, bh[nf]);
        }
        __syncthreads();
    }

    // ---- epilogue: bias + store (float2 per row-fragment) ----
    const int mr0 = m0 + gid;
    const int mr1 = m0 + gid + 8;
    #pragma unroll
    for (int nf = 0; nf < NF; nf++) {
        int nn = n0blk + n0w + nf * 8 + tig * 2;
        float b0 = bias1[nn]     + (CONCAT ? bias2[nn]     : 0.f);
        float b1 = bias1[nn + 1] + (CONCAT ? bias2[nn + 1] : 0.f);
        float2 v0 = make_float2(c[nf][0] + b0, c[nf][1] + b1);
        float2 v1 = make_float2(c[nf][2] + b0, c[nf][3] + b1);
        *reinterpret_cast<float2*>(out + (size_t)mr0 * ldc + nn) = v0;
        *reinterpret_cast<float2*>(out + (size_t)mr1 * ldc + nn) = v1;
    }
}

// ---------------------------------------------------------------------------
// LSTM cell elementwise (PyTorch gate order i,f,g,o)
// ---------------------------------------------------------------------------
__global__ void cell_kernel() {
    int i = blockIdx.x * blockDim.x + threadIdx.x;   // B*H
    int b = i >> 10;
    int j = i & (H - 1);
    const float* g = g_gates + b * GATES;
    float ig = g[j], fg = g[j + H], gg = g[j + 2 * H], og = g[j + 3 * H];
    float c  = g_c[i];
    float si = 1.f / (1.f + expf(-ig));
    float sf = 1.f / (1.f + expf(-fg));
    float so = 1.f / (1.f + expf(-og));
    float cn = sf * c + si * tanhf(gg);
    float hn = so * tanhf(cn);
    g_c[i] = cn;
    g_h[i] = hn;
}

// ---------------------------------------------------------------------------
// Per-batch-row: argmax (first-index tiebreak), softmax EOS prob,
// greedy feedback gather x_next = E[argmax]. 1024 threads, float4 loads.
// ---------------------------------------------------------------------------
__global__ __launch_bounds__(1024)
void softmax_argmax(const float* __restrict__ logits, const float* __restrict__ E,
                    float* __restrict__ mask_out) {
    const int b    = blockIdx.x;
    const int tid  = threadIdx.x;
    const int lane = tid & 31;
    const int wrp  = tid >> 5;
    const float* row = logits + (size_t)b * V;

    // ---- pass 1: max + argmax (lowest index on ties) ----
    float best = -INFINITY; int besti = 0x7fffffff;
    for (int v = tid * 4; v < V; v += 4096) {
        float4 x = *reinterpret_cast<const float4*>(row + v);
        if (x.x > best) { best = x.x; besti = v; }
        if (x.y > best) { best = x.y; besti = v + 1; }
        if (x.z > best) { best = x.z; besti = v + 2; }
        if (x.w > best) { best = x.w; besti = v + 3; }
    }
    #pragma unroll
    for (int s = 16; s > 0; s >>= 1) {
        float ov = __shfl_down_sync(0xffffffffu, best, s);
        int   oi = __shfl_down_sync(0xffffffffu, besti, s);
        if (ov > best || (ov == best && oi < besti)) { best = ov; besti = oi; }
    }
    __shared__ float swv[32];
    __shared__ int   swi[32];
    if (lane == 0) { swv[wrp] = best; swi[wrp] = besti; }
    __syncthreads();
    __shared__ float s_gmax;
    __shared__ int   s_amax;
    if (wrp == 0) {
        float bv = swv[lane]; int bi = swi[lane];
        #pragma unroll
        for (int s = 16; s > 0; s >>= 1) {
            float ov = __shfl_down_sync(0xffffffffu, bv, s);
            int   oi = __shfl_down_sync(0xffffffffu, bi, s);
            if (ov > bv || (ov == bv && oi < bi)) { bv = ov; bi = oi; }
        }
        if (lane == 0) { s_gmax = bv; s_amax = bi; }
    }
    __syncthreads();
    const float gmax = s_gmax;
    const int   amax = s_amax;

    // ---- pass 2: sum of exp ----
    float sum = 0.f;
    for (int v = tid * 4; v < V; v += 4096) {
        float4 x = *reinterpret_cast<const float4*>(row + v);
        sum += expf(x.x - gmax) + expf(x.y - gmax)
             + expf(x.z - gmax) + expf(x.w - gmax);
    }
    #pragma unroll
    for (int s = 16; s > 0; s >>= 1)
        sum += __shfl_down_sync(0xffffffffu, sum, s);
    __shared__ float ssum[32];
    if (lane == 0) ssum[wrp] = sum;
    __syncthreads();
    if (wrp == 0) {
        float t = ssum[lane];
        #pragma unroll
        for (int s = 16; s > 0; s >>= 1)
            t += __shfl_down_sync(0xffffffffu, t, s);
        if (lane == 0) mask_out[b] = expf(row[EOS_INDEX] - gmax) / t;
    }

    // greedy feedback: x_next = E[argmax]  (H == 1024 == blockDim)
    g_x[b * H + tid] = E[(size_t)amax * H + tid];
}

// ---------------------------------------------------------------------------
extern "C" void kernel_launch(void* const* d_in, const int* in_sizes, int n_in,
                              void* d_out, int out_size) {
    const float* E    = (const float*)d_in[0];
    const float* Wih  = (const float*)d_in[1];
    const float* Whh  = (const float*)d_in[2];
    const float* bih  = (const float*)d_in[3];
    const float* bhh  = (const float*)d_in[4];
    const float* Wout = (const float*)d_in[5];
    const float* bout = (const float*)d_in[6];
    const float* eh   = (const float*)d_in[7];
    const float* ec   = (const float*)d_in[8];

    float* out   = (float*)d_out;                       // [T][B][V] logits
    float* masks = out + (size_t)T * B * V;             // [T][B]

    // Resolve DEVICE address of g_gates (host shadow addr would silently
    // write host memory via ATS on GB300).
    void* gates_dev = nullptr;
    cudaGetSymbolAddress(&gates_dev, g_gates);
    float* gates_ptr = (float*)gates_dev;

    init_kernel<<<(B * H) / 256, 256>>>(E, eh, ec);
    for (int t = 0; t < T; t++) {
        float* lg = out + (size_t)t * B * V;
        // gates: [64 x 4096] = [x|h] * [Wih|Whh]^T, BN=32 -> 128 blocks
        mma_gemm<2 * H, 32, true><<<GATES / 32, 256>>>(
            Wih, Whh, bih, bhh, gates_ptr, GATES);
        cell_kernel<<<(B * H) / 256, 256>>>();
        // logits: [64 x 32000] = h * Wout^T, BN=64 -> 500 blocks
        mma_gemm<H, 64, false><<<V / 64, 256>>>(
            Wout, nullptr, bout, nullptr, lg, V);
        softmax_argmax<<<B, 1024>>>(lg, E, masks + t * B);
    }
}

// round 6
// speedup vs baseline: 1.5183x; 1.5183x over previous
#include <cuda_runtime.h>
#include <math.h>
#include <stdint.h>

#define V 32000
#define H 1024
#define T 32
#define B 64
#define SOS_INDEX 1
#define EOS_INDEX 2
#define GATES (4*H)

// Persistent decode state (no allocations allowed)
__device__ float g_x[B*H];       // current input embedding
__device__ float g_h[B*H];       // hidden state
__device__ float g_c[B*H];       // cell state
__device__ float g_gates[B*GATES];

// ---------------------------------------------------------------------------
__global__ void init_kernel(const float* __restrict__ E,
                            const float* __restrict__ eh,
                            const float* __restrict__ ec) {
    int i = blockIdx.x * blockDim.x + threadIdx.x;   // 0 .. B*H
    int k = i & (H - 1);
    g_x[i] = E[SOS_INDEX * H + k];
    g_h[i] = eh[i];
    g_c[i] = ec[i];
}

// ---------------------------------------------------------------------------
// TF32 helpers (3xTF32 fp32 emulation)
// ---------------------------------------------------------------------------
__device__ __forceinline__ uint32_t f2tf32(float x) {
    uint32_t r;
    asm("cvt.rna.tf32.f32 %0, %1;" : "=r"(r) : "f"(x));
    return r;
}
__device__ __forceinline__ void split_tf32(float x, float& hi, float& lo) {
    hi = __uint_as_float(f2tf32(x));
    lo = __uint_as_float(f2tf32(x - hi));
}
__device__ __forceinline__ void mma_tf32(float c[4], const uint32_t a[4],
                                         const uint32_t b[2]) {
    asm volatile(
        "mma.sync.aligned.m16n8k8.row.col.f32.tf32.tf32.f32 "
        "{%0,%1,%2,%3}, {%4,%5,%6,%7}, {%8,%9}, {%0,%1,%2,%3};"
        : "+f"(c[0]), "+f"(c[1]), "+f"(c[2]), "+f"(c[3])
        : "r"(a[0]), "r"(a[1]), "r"(a[2]), "r"(a[3]), "r"(b[0]), "r"(b[1]));
}
__device__ __forceinline__ void ldsm4(uint32_t r[4], uint32_t addr) {
    asm volatile(
        "ldmatrix.sync.aligned.m8n8.x4.shared.b16 {%0,%1,%2,%3}, [%4];"
        : "=r"(r[0]), "=r"(r[1]), "=r"(r[2]), "=r"(r[3]) : "r"(addr));
}

// ---------------------------------------------------------------------------
// Tensor-core GEMM: C[64 x N] = A[64 x KTOT] * W[N x KTOT]^T + bias
// Element-major SMEM tiles (merged STS.128 at store, hi/lo split done once),
// ldmatrix.x4 consumers (6 LDSM per k8-step feed 12 HMMAs).
// ---------------------------------------------------------------------------
#define BK 32
#define SKEW 4
#define ROWB ((BK + SKEW) * 4)   // 144 bytes per tile row (16B-aligned)

template<int KTOT, int BN, bool CONCAT>
__global__ __launch_bounds__(256)
void mma_gemm(const float* __restrict__ Wa, const float* __restrict__ Wb,
              const float* __restrict__ bias1, const float* __restrict__ bias2,
              float* __restrict__ out, int ldc) {
    constexpr int NF = BN / 16;           // n8 fragments per warp (2 or 4)
    constexpr int BR = BN / 32;           // B loader row chunks
    __shared__ __align__(16) float AsH[64][BK + SKEW];
    __shared__ __align__(16) float AsL[64][BK + SKEW];
    __shared__ __align__(16) float BsH[BN][BK + SKEW];
    __shared__ __align__(16) float BsL[BN][BK + SKEW];

    const int n0blk = blockIdx.x * BN;
    const int tid   = threadIdx.x;
    const int warp  = tid >> 5;
    const int lane  = tid & 31;
    const int gid   = lane >> 2;
    const int tig   = lane & 3;

    const int m0  = (warp >> 1) * 16;      // warp M offset (0,16,32,48)
    const int n0w = (warp & 1) * (BN / 2); // warp N offset

    const int lm  = tid >> 3;              // loader row 0..31
    const int lk4 = (tid & 7) * 4;         // loader k offset (float4)

    // ldmatrix lane addressing (PTX m8n8.x4: lanes 0-7/8-15/16-23/24-31 ->
    // matrices 0..3). A frag: (rows m0+lane&15, k-half (lane>>4)&1).
    const int a_row = m0 + (lane & 15);
    const int a_col = 4 * ((lane >> 4) & 1);
    const uint32_t aH = (uint32_t)__cvta_generic_to_shared(&AsH[a_row][a_col]);
    const uint32_t aL = (uint32_t)__cvta_generic_to_shared(&AsL[a_row][a_col]);
    // B frag pair: rows n0w+(lane&7)+8*((lane>>4)&1), k-half (lane>>3)&1.
    const int b_row = n0w + (lane & 7) + 8 * ((lane >> 4) & 1);
    const int b_col = 4 * ((lane >> 3) & 1);
    const uint32_t bH = (uint32_t)__cvta_generic_to_shared(&BsH[b_row][b_col]);
    const uint32_t bL = (uint32_t)__cvta_generic_to_shared(&BsL[b_row][b_col]);

    float4 aR[2];
    float4 bR[BR];

    auto gload = [&](int k0) {
        const int kg = k0 + lk4;
        #pragma unroll
        for (int r = 0; r < 2; r++) {
            int m = lm + r * 32;
            const float* src = CONCAT
                ? ((kg < H) ? (g_x + m * H + kg) : (g_h + m * H + (kg - H)))
                : (g_h + m * H + kg);
            aR[r] = *reinterpret_cast<const float4*>(src);
        }
        #pragma unroll
        for (int r = 0; r < BR; r++) {
            int n = lm + r * 32;
            const float* src = CONCAT
                ? ((kg < H) ? (Wa + (size_t)(n0blk + n) * H + kg)
                            : (Wb + (size_t)(n0blk + n) * H + (kg - H)))
                : (Wa + (size_t)(n0blk + n) * KTOT + kg);
            bR[r] = *reinterpret_cast<const float4*>(src);
        }
    };

    auto store_split = [&]() {
        #pragma unroll
        for (int r = 0; r < 2; r++) {
            int m = lm + r * 32;
            float v[4] = {aR[r].x, aR[r].y, aR[r].z, aR[r].w};
            float h[4], l[4];
            #pragma unroll
            for (int j = 0; j < 4; j++) split_tf32(v[j], h[j], l[j]);
            *reinterpret_cast<float4*>(&AsH[m][lk4]) = make_float4(h[0], h[1], h[2], h[3]);
            *reinterpret_cast<float4*>(&AsL[m][lk4]) = make_float4(l[0], l[1], l[2], l[3]);
        }
        #pragma unroll
        for (int r = 0; r < BR; r++) {
            int n = lm + r * 32;
            float v[4] = {bR[r].x, bR[r].y, bR[r].z, bR[r].w};
            float h[4], l[4];
            #pragma unroll
            for (int j = 0; j < 4; j++) split_tf32(v[j], h[j], l[j]);
            *reinterpret_cast<float4*>(&BsH[n][lk4]) = make_float4(h[0], h[1], h[2], h[3]);
            *reinterpret_cast<float4*>(&BsL[n][lk4]) = make_float4(l[0], l[1], l[2], l[3]);
        }
    };

    float c[NF][4];
    #pragma unroll
    for (int nf = 0; nf < NF; nf++)
        #pragma unroll
        for (int j = 0; j < 4; j++) c[nf][j] = 0.f;

    gload(0);
    for (int k0 = 0; k0 < KTOT; k0 += BK) {
        store_split();
        __syncthreads();
        if (k0 + BK < KTOT) gload(k0 + BK);    // prefetch next tile into regs

        #pragma unroll
        for (int ks = 0; ks < BK / 8; ks++) {
            const uint32_t koff = ks * 32;     // 8 tf32 = 32 bytes
            uint32_t ah[4], al[4];
            ldsm4(ah, aH + koff);
            ldsm4(al, aL + koff);
            uint32_t bh[2 * NF], bl[2 * NF];
            #pragma unroll
            for (int p = 0; p < NF / 2; p++) { // one x4 = two n8 frags
                ldsm4(&bh[4 * p], bH + koff + p * 16 * ROWB);
                ldsm4(&bl[4 * p], bL + koff + p * 16 * ROWB);
            }
            // 3xTF32: C += Al*Bh + Ah*Bl + Ah*Bh, pass-major ordering
            #pragma unroll
            for (int nf = 0; nf < NF; nf++) mma_tf32(c[nf], al, &bh[2 * nf]);
            #pragma unroll
            for (int nf = 0; nf < NF; nf++) mma_tf32(c[nf], ah, &bl[2 * nf]);
            #pragma unroll
            for (int nf = 0; nf < NF; nf++) mma_tf32(c[nf], ah, &bh[2 * nf]);
        }
        __syncthreads();
    }

    // ---- epilogue: bias + store (float2 per row-fragment) ----
    const int mr0 = m0 + gid;
    const int mr1 = m0 + gid + 8;
    #pragma unroll
    for (int nf = 0; nf < NF; nf++) {
        int nn = n0blk + n0w + nf * 8 + tig * 2;
        float b0 = bias1[nn]     + (CONCAT ? bias2[nn]     : 0.f);
        float b1 = bias1[nn + 1] + (CONCAT ? bias2[nn + 1] : 0.f);
        float2 v0 = make_float2(c[nf][0] + b0, c[nf][1] + b1);
        float2 v1 = make_float2(c[nf][2] + b0, c[nf][3] + b1);
        *reinterpret_cast<float2*>(out + (size_t)mr0 * ldc + nn) = v0;
        *reinterpret_cast<float2*>(out + (size_t)mr1 * ldc + nn) = v1;
    }
}

// ---------------------------------------------------------------------------
// LSTM cell elementwise (PyTorch gate order i,f,g,o)
// ---------------------------------------------------------------------------
__global__ void cell_kernel() {
    int i = blockIdx.x * blockDim.x + threadIdx.x;   // B*H
    int b = i >> 10;
    int j = i & (H - 1);
    const float* g = g_gates + b * GATES;
    float ig = g[j], fg = g[j + H], gg = g[j + 2 * H], og = g[j + 3 * H];
    float c  = g_c[i];
    float si = 1.f / (1.f + expf(-ig));
    float sf = 1.f / (1.f + expf(-fg));
    float so = 1.f / (1.f + expf(-og));
    float cn = sf * c + si * tanhf(gg);
    float hn = so * tanhf(cn);
    g_c[i] = cn;
    g_h[i] = hn;
}

// ---------------------------------------------------------------------------
// Per-batch-row: argmax (first-index tiebreak), softmax EOS prob,
// greedy feedback gather x_next = E[argmax]. 1024 threads, float4 loads.
// ---------------------------------------------------------------------------
__global__ __launch_bounds__(1024)
void softmax_argmax(const float* __restrict__ logits, const float* __restrict__ E,
                    float* __restrict__ mask_out) {
    const int b    = blockIdx.x;
    const int tid  = threadIdx.x;
    const int lane = tid & 31;
    const int wrp  = tid >> 5;
    const float* row = logits + (size_t)b * V;

    // ---- pass 1: max + argmax (lowest index on ties) ----
    float best = -INFINITY; int besti = 0x7fffffff;
    for (int v = tid * 4; v < V; v += 4096) {
        float4 x = *reinterpret_cast<const float4*>(row + v);
        if (x.x > best) { best = x.x; besti = v; }
        if (x.y > best) { best = x.y; besti = v + 1; }
        if (x.z > best) { best = x.z; besti = v + 2; }
        if (x.w > best) { best = x.w; besti = v + 3; }
    }
    #pragma unroll
    for (int s = 16; s > 0; s >>= 1) {
        float ov = __shfl_down_sync(0xffffffffu, best, s);
        int   oi = __shfl_down_sync(0xffffffffu, besti, s);
        if (ov > best || (ov == best && oi < besti)) { best = ov; besti = oi; }
    }
    __shared__ float swv[32];
    __shared__ int   swi[32];
    if (lane == 0) { swv[wrp] = best; swi[wrp] = besti; }
    __syncthreads();
    __shared__ float s_gmax;
    __shared__ int   s_amax;
    if (wrp == 0) {
        float bv = swv[lane]; int bi = swi[lane];
        #pragma unroll
        for (int s = 16; s > 0; s >>= 1) {
            float ov = __shfl_down_sync(0xffffffffu, bv, s);
            int   oi = __shfl_down_sync(0xffffffffu, bi, s);
            if (ov > bv || (ov == bv && oi < bi)) { bv = ov; bi = oi; }
        }
        if (lane == 0) { s_gmax = bv; s_amax = bi; }
    }
    __syncthreads();
    const float gmax = s_gmax;
    const int   amax = s_amax;

    // ---- pass 2: sum of exp ----
    float sum = 0.f;
    for (int v = tid * 4; v < V; v += 4096) {
        float4 x = *reinterpret_cast<const float4*>(row + v);
        sum += expf(x.x - gmax) + expf(x.y - gmax)
             + expf(x.z - gmax) + expf(x.w - gmax);
    }
    #pragma unroll
    for (int s = 16; s > 0; s >>= 1)
        sum += __shfl_down_sync(0xffffffffu, sum, s);
    __shared__ float ssum[32];
    if (lane == 0) ssum[wrp] = sum;
    __syncthreads();
    if (wrp == 0) {
        float t = ssum[lane];
        #pragma unroll
        for (int s = 16; s > 0; s >>= 1)
            t += __shfl_down_sync(0xffffffffu, t, s);
        if (lane == 0) mask_out[b] = expf(row[EOS_INDEX] - gmax) / t;
    }

    // greedy feedback: x_next = E[argmax]  (H == 1024 == blockDim)
    g_x[b * H + tid] = E[(size_t)amax * H + tid];
}

// ---------------------------------------------------------------------------
extern "C" void kernel_launch(void* const* d_in, const int* in_sizes, int n_in,
                              void* d_out, int out_size) {
    const float* E    = (const float*)d_in[0];
    const float* Wih  = (const float*)d_in[1];
    const float* Whh  = (const float*)d_in[2];
    const float* bih  = (const float*)d_in[3];
    const float* bhh  = (const float*)d_in[4];
    const float* Wout = (const float*)d_in[5];
    const float* bout = (const float*)d_in[6];
    const float* eh   = (const float*)d_in[7];
    const float* ec   = (const float*)d_in[8];

    float* out   = (float*)d_out;                       // [T][B][V] logits
    float* masks = out + (size_t)T * B * V;             // [T][B]

    // Resolve DEVICE address of g_gates (host shadow addr would silently
    // write host memory via ATS on GB300).
    void* gates_dev = nullptr;
    cudaGetSymbolAddress(&gates_dev, g_gates);
    float* gates_ptr = (float*)gates_dev;

    init_kernel<<<(B * H) / 256, 256>>>(E, eh, ec);
    for (int t = 0; t < T; t++) {
        float* lg = out + (size_t)t * B * V;
        // gates: [64 x 4096] = [x|h] * [Wih|Whh]^T, BN=32 -> 128 blocks
        mma_gemm<2 * H, 32, true><<<GATES / 32, 256>>>(
            Wih, Whh, bih, bhh, gates_ptr, GATES);
        cell_kernel<<<(B * H) / 256, 256>>>();
        // logits: [64 x 32000] = h * Wout^T, BN=64 -> 500 blocks
        mma_gemm<H, 64, false><<<V / 64, 256>>>(
            Wout, nullptr, bout, nullptr, lg, V);
        softmax_argmax<<<B, 1024>>>(lg, E, masks + t * B);
    }
}